// round 4
// baseline (speedup 1.0000x reference)
#include <cuda_runtime.h>
#include <cuda_bf16.h>
#include <stdint.h>

#define C_IN   32
#define C_OUT  32
#define KD     27
#define TM     128          // nodes per CTA
#define GPAD   36           // padded row stride for gather tile (floats)

__device__ int g_neigh_is64;   // 1 if neigh buffer is int64, 0 if int32

// Detect neigh dtype: view buffer as int32 words; if int64 (little-endian),
// every odd word is a hi-word and must be 0 (valid idx) or -1 (invalid).
// 1024 samples of random int32 indices fake that with P ~ 0.
__global__ void detect_dtype_kernel(const int* __restrict__ w, long long n_words32)
{
    __shared__ int ok;
    if (threadIdx.x == 0) ok = 1;
    __syncthreads();
    const long long pos = 2LL * threadIdx.x + 1;
    if (pos < n_words32) {
        const int v = w[pos];
        if (v != 0 && v != -1) ok = 0;
    }
    __syncthreads();
    if (threadIdx.x == 0) g_neigh_is64 = ok;
}

__global__ __launch_bounds__(TM) void octconv_kernel(
    const float* __restrict__ data,          // [N, 32]
    const float* __restrict__ weights,       // [27, 32, 32]
    const void* __restrict__ neigh_raw,      // [N, 27] i32 or i64
    float* __restrict__ out,                 // [N, 32]
    int N)
{
    __shared__ int   sidx[KD * TM];          // [k][row]
    __shared__ float sg[TM][GPAD];           // padded: stride 36 -> conflict-free LDS.128
    __shared__ float sw[C_IN][C_OUT];        // one k-slice of weights

    const int tid  = threadIdx.x;
    const int warp = tid >> 5;
    const int lane = tid & 31;
    const int base = blockIdx.x * TM;
    const bool is64 = (g_neigh_is64 != 0);   // uniform branch
    const int*       n32 = (const int*)neigh_raw;
    const long long* n64 = (const long long*)neigh_raw;

    // ---- Load all neighbor indices for this tile ----
    for (int i = tid; i < TM * KD; i += TM) {
        const int row  = i / KD;
        const int k    = i % KD;
        const int node = base + row;
        int v = -1;
        if (node < N) {
            const long long e = (long long)node * KD + k;
            v = is64 ? (int)n64[e] : n32[e];
        }
        sidx[k * TM + row] = v;
    }
    __syncthreads();          // <-- FIX: sidx is read cross-thread in the gather

    float acc[C_OUT];
    #pragma unroll
    for (int o = 0; o < C_OUT; o++) acc[o] = 0.0f;

    for (int k = 0; k < KD; k++) {
        // ---- gather: each warp loads 32 rows, coalesced 128B rows ----
        #pragma unroll 4
        for (int i = 0; i < 32; i++) {
            const int row = (warp << 5) + i;
            const int idx = sidx[k * TM + row];
            float v = 0.0f;
            if (idx >= 0 && idx < N) v = data[idx * C_IN + lane];
            sg[row][lane] = v;
        }
        // ---- stage weights[k] (4KB) ----
        {
            const float* wk = weights + k * C_IN * C_OUT;
            #pragma unroll
            for (int i = 0; i < (C_IN * C_OUT) / TM; i++)
                (&sw[0][0])[i * TM + tid] = wk[i * TM + tid];
        }
        __syncthreads();

        // ---- compute: thread owns node 'tid', 32 outputs in registers ----
        const float4* g4 = (const float4*)(&sg[tid][0]);   // 144B row stride, 16B aligned
        #pragma unroll
        for (int c4 = 0; c4 < C_IN / 4; c4++) {
            const float4 g = g4[c4];
            #pragma unroll
            for (int j = 0; j < 4; j++) {
                const float v = (j == 0) ? g.x : (j == 1) ? g.y : (j == 2) ? g.z : g.w;
                const float4* wr = (const float4*)(&sw[c4 * 4 + j][0]);  // broadcast LDS
                #pragma unroll
                for (int o4 = 0; o4 < C_OUT / 4; o4++) {
                    const float4 w = wr[o4];
                    acc[o4 * 4 + 0] += v * w.x;
                    acc[o4 * 4 + 1] += v * w.y;
                    acc[o4 * 4 + 2] += v * w.z;
                    acc[o4 * 4 + 3] += v * w.w;
                }
            }
        }
        __syncthreads();   // protect sg/sw reuse next k
    }

    // ---- epilogue: transpose through smem for coalesced stores ----
    #pragma unroll
    for (int o = 0; o < C_OUT; o++) sg[tid][o] = acc[o];
    __syncthreads();
    #pragma unroll 4
    for (int i = 0; i < 32; i++) {
        const int row  = (warp << 5) + i;
        const int node = base + row;
        if (node < N) out[node * C_OUT + lane] = sg[row][lane];
    }
}

extern "C" void kernel_launch(void* const* d_in, const int* in_sizes, int n_in,
                              void* d_out, int out_size)
{
    // Identify inputs by element count (robust to metadata ordering):
    //   weights: 27*32*32 = 27648 (smallest)
    //   data:    N*32 (largest)     neigh: N*27 (middle)
    long long s[3] = { (long long)in_sizes[0], (long long)in_sizes[1], (long long)in_sizes[2] };
    int iw  = (s[0] <= s[1] && s[0] <= s[2]) ? 0 : (s[1] <= s[2] ? 1 : 2);
    int idt = (s[0] >= s[1] && s[0] >= s[2]) ? 0 : (s[1] >= s[2] ? 1 : 2);
    if (iw == idt) { iw = 1; idt = 0; }            // degenerate safety
    int ing = 3 - iw - idt;

    const float* data    = (const float*)d_in[idt];
    const float* weights = (const float*)d_in[iw];
    const void*  neigh   = d_in[ing];
    float*       out     = (float*)d_out;

    const int N = (int)(s[idt] / C_IN);
    const long long neigh_words32 = s[ing];   // conservative word count for both dtypes

    detect_dtype_kernel<<<1, 1024>>>((const int*)neigh, neigh_words32);

    const int grid = (N + TM - 1) / TM;
    octconv_kernel<<<grid, TM>>>(data, weights, neigh, out, N);
}

// round 5
// speedup vs baseline: 2.5861x; 2.5861x over previous
#include <cuda_runtime.h>
#include <cuda_bf16.h>
#include <stdint.h>

#define C_IN   32
#define C_OUT  32
#define KD     27
#define TPB    128        // threads per CTA
#define TM     256        // nodes per CTA (2 per thread)
#define GPAD   36         // gather row stride in floats (144B): conflict-free float4 reads

__device__ int g_neigh_is64;   // 1 if neigh buffer is int64, 0 if int32

// Detect neigh dtype: view as int32 words; if int64 (LE), every odd word is a
// hi-word and must be 0 or -1. 1024 samples -> unambiguous for random int32.
__global__ void detect_dtype_kernel(const int* __restrict__ w, long long n_words32)
{
    __shared__ int ok;
    if (threadIdx.x == 0) ok = 1;
    __syncthreads();
    const long long pos = 2LL * threadIdx.x + 1;
    if (pos < n_words32) {
        const int v = w[pos];
        if (v != 0 && v != -1) ok = 0;
    }
    __syncthreads();
    if (threadIdx.x == 0) g_neigh_is64 = ok;
}

__device__ __forceinline__ unsigned long long ffma2(unsigned long long a,
                                                    unsigned long long b,
                                                    unsigned long long c)
{
    unsigned long long d;
    asm("fma.rn.f32x2 %0, %1, %2, %3;" : "=l"(d) : "l"(a), "l"(b), "l"(c));
    return d;
}

__device__ __forceinline__ unsigned long long packf2(float x, float y)
{
    unsigned long long d;
    asm("mov.b64 %0, {%1, %2};" : "=l"(d) : "f"(x), "f"(y));
    return d;
}

__device__ __forceinline__ void unpackf2(unsigned long long v, float& x, float& y)
{
    asm("mov.b64 {%0, %1}, %2;" : "=f"(x), "=f"(y) : "l"(v));
}

__device__ __forceinline__ void cpasync16(uint32_t dst_smem, const void* src, int src_sz)
{
    asm volatile("cp.async.cg.shared.global [%0], [%1], 16, %2;"
                 :: "r"(dst_smem), "l"(src), "r"(src_sz));
}

__global__ __launch_bounds__(TPB) void octconv_kernel(
    const float* __restrict__ data,          // [N, 32]
    const float* __restrict__ weights,       // [27, 32, 32]
    const void* __restrict__ neigh_raw,      // [N, 27] i32 or i64
    float* __restrict__ out,                 // [N, 32]
    int N)
{
    __shared__ float sg[TM][GPAD];           // 36864B gather tile
    __shared__ float sw[C_IN][C_OUT];        // 4096B one k-slice; o-pairs contiguous
    __shared__ int   sidxk[TM];              // 1024B per-k indices (warp-private slices)

    const int tid  = threadIdx.x;
    const int warp = tid >> 5;
    const int lane = tid & 31;
    const int base = blockIdx.x * TM;
    const bool is64 = (g_neigh_is64 != 0);   // uniform branch
    const int*       n32 = (const int*)neigh_raw;
    const long long* n64 = (const long long*)neigh_raw;

    uint32_t sg_base;
    asm("{ .reg .u64 t; cvta.to.shared.u64 t, %1; cvt.u32.u64 %0, t; }"
        : "=r"(sg_base) : "l"(&sg[0][0]));
    uint32_t sw_base;
    asm("{ .reg .u64 t; cvta.to.shared.u64 t, %1; cvt.u32.u64 %0, t; }"
        : "=r"(sw_base) : "l"(&sw[0][0]));

    // packed accumulators: 16 f32x2 pairs per node
    unsigned long long acc0[C_OUT / 2], acc1[C_OUT / 2];
    #pragma unroll
    for (int i = 0; i < C_OUT / 2; i++) { acc0[i] = 0ull; acc1[i] = 0ull; }

    const int subrow = lane >> 3;            // 0..3
    const int quad   = lane & 7;             // 0..7  (16B chunk within row)

    for (int k = 0; k < KD; k++) {
        // ---- stage weights[k] (4KB) via cp.async ----
        {
            const float4* wk4 = (const float4*)(weights + k * C_IN * C_OUT);
            cpasync16(sw_base + tid * 16,            wk4 + tid,        16);
            cpasync16(sw_base + (tid + TPB) * 16,    wk4 + tid + TPB,  16);
        }

        // ---- per-k neighbor indices for this warp's 64 rows ----
        {
            const int r0 = 64 * warp + lane;
            const int r1 = r0 + 32;
            int i0 = -1, i1 = -1;
            if (base + r0 < N) {
                const long long e = (long long)(base + r0) * KD + k;
                i0 = is64 ? (int)n64[e] : n32[e];
            }
            if (base + r1 < N) {
                const long long e = (long long)(base + r1) * KD + k;
                i1 = is64 ? (int)n64[e] : n32[e];
            }
            sidxk[r0] = i0;
            sidxk[r1] = i1;
            __syncwarp();
        }

        // ---- gather: 4 rows per warp-step, 16B per lane, zero-fill invalid ----
        #pragma unroll 4
        for (int j = 0; j < 16; j++) {
            const int row = 64 * warp + 4 * j + subrow;
            const int idx = sidxk[row];
            const int ok  = (idx >= 0 && idx < N);
            const int sz  = ok ? 16 : 0;
            const float* src = data + (long long)(ok ? idx : 0) * C_IN + quad * 4;
            cpasync16(sg_base + row * (GPAD * 4) + quad * 16, src, sz);
        }
        asm volatile("cp.async.commit_group;");
        asm volatile("cp.async.wait_group 0;" ::: "memory");
        __syncthreads();

        // ---- compute: thread owns nodes tid and tid+128, packed f32x2 FMAs ----
        const float4* g0 = (const float4*)(&sg[tid][0]);
        const float4* g1 = (const float4*)(&sg[tid + TPB][0]);
        #pragma unroll
        for (int c4 = 0; c4 < C_IN / 4; c4++) {
            const float4 a0 = g0[c4];
            const float4 a1 = g1[c4];
            #pragma unroll
            for (int j = 0; j < 4; j++) {
                const float v0 = (j == 0) ? a0.x : (j == 1) ? a0.y : (j == 2) ? a0.z : a0.w;
                const float v1 = (j == 0) ? a1.x : (j == 1) ? a1.y : (j == 2) ? a1.z : a1.w;
                const unsigned long long p0 = packf2(v0, v0);
                const unsigned long long p1 = packf2(v1, v1);
                const ulonglong2* wr = (const ulonglong2*)(&sw[c4 * 4 + j][0]); // 8 vec2 of pairs
                #pragma unroll
                for (int q = 0; q < 8; q++) {
                    const ulonglong2 w = wr[q];     // pairs (4q,4q+1),(4q+2,4q+3)
                    acc0[2 * q]     = ffma2(p0, w.x, acc0[2 * q]);
                    acc0[2 * q + 1] = ffma2(p0, w.y, acc0[2 * q + 1]);
                    acc1[2 * q]     = ffma2(p1, w.x, acc1[2 * q]);
                    acc1[2 * q + 1] = ffma2(p1, w.y, acc1[2 * q + 1]);
                }
            }
        }
        __syncthreads();   // sg/sw free for next k
    }

    // ---- epilogue: two transpose rounds through sg for coalesced stores ----
    #pragma unroll
    for (int i = 0; i < C_OUT / 2; i++) {
        float x, y;
        unpackf2(acc0[i], x, y);
        sg[tid][2 * i] = x;  sg[tid][2 * i + 1] = y;
        unpackf2(acc1[i], x, y);
        sg[tid + TPB][2 * i] = x;  sg[tid + TPB][2 * i + 1] = y;
    }
    __syncthreads();
    #pragma unroll 4
    for (int i = 0; i < TM / 4; i++) {       // 4 warps cover 256 rows
        const int row  = warp * (TM / 4) + i;
        const int node = base + row;
        if (node < N) out[node * C_OUT + lane] = sg[row][lane];
    }
}

extern "C" void kernel_launch(void* const* d_in, const int* in_sizes, int n_in,
                              void* d_out, int out_size)
{
    // Identify inputs by element count (robust to metadata ordering):
    //   weights: 27*32*32 = 27648 (smallest); data: N*32 (largest); neigh: N*27
    long long s[3] = { (long long)in_sizes[0], (long long)in_sizes[1], (long long)in_sizes[2] };
    int iw  = (s[0] <= s[1] && s[0] <= s[2]) ? 0 : (s[1] <= s[2] ? 1 : 2);
    int idt = (s[0] >= s[1] && s[0] >= s[2]) ? 0 : (s[1] >= s[2] ? 1 : 2);
    if (iw == idt) { iw = 1; idt = 0; }
    int ing = 3 - iw - idt;

    const float* data    = (const float*)d_in[idt];
    const float* weights = (const float*)d_in[iw];
    const void*  neigh   = d_in[ing];
    float*       out     = (float*)d_out;

    const int N = (int)(s[idt] / C_IN);
    detect_dtype_kernel<<<1, 1024>>>((const int*)neigh, s[ing]);

    const int grid = (N + TM - 1) / TM;
    octconv_kernel<<<grid, TPB>>>(data, weights, neigh, out, N);
}

// round 7
// speedup vs baseline: 3.3309x; 1.2880x over previous
#include <cuda_runtime.h>
#include <cuda_bf16.h>
#include <stdint.h>

#define C_IN   32
#define C_OUT  32
#define KD     27
#define TPB    128
#define TM     128
#define MAXN   262144

// ---------------- device scratch ----------------
__device__ __align__(256) __nv_bfloat16 g_pack[MAXN * 64];   // [N][128B]: hi(32bf16)|lo(32bf16)
__device__ __align__(256) uint2 g_bfrag[KD * 16 * 32];       // [k][frag f=((v*2+s)*4+nt)][lane]
__device__ int g_neigh_is64;

// ---------------- helpers ----------------
__device__ __forceinline__ uint32_t s2u(const void* p) {
    uint32_t a;
    asm("{ .reg .u64 t; cvta.to.shared.u64 t, %1; cvt.u32.u64 %0, t; }" : "=r"(a) : "l"(p));
    return a;
}
__device__ __forceinline__ void cpasync16(uint32_t dst, const void* src, int sz) {
    asm volatile("cp.async.cg.shared.global [%0], [%1], 16, %2;" :: "r"(dst), "l"(src), "r"(sz));
}
#define SW128(x) ((x) ^ (((x) >> 3) & 0x70))

__device__ __forceinline__ void ldsm4(uint32_t* r, uint32_t addr) {
    asm volatile("ldmatrix.sync.aligned.m8n8.x4.shared.b16 {%0,%1,%2,%3}, [%4];"
                 : "=r"(r[0]), "=r"(r[1]), "=r"(r[2]), "=r"(r[3]) : "r"(addr));
}
__device__ __forceinline__ void mma16816(float* c, const uint32_t* a, uint2 b) {
    asm volatile("mma.sync.aligned.m16n8k16.row.col.f32.bf16.bf16.f32 "
                 "{%0,%1,%2,%3}, {%4,%5,%6,%7}, {%8,%9}, {%0,%1,%2,%3};"
                 : "+f"(c[0]), "+f"(c[1]), "+f"(c[2]), "+f"(c[3])
                 : "r"(a[0]), "r"(a[1]), "r"(a[2]), "r"(a[3]), "r"(b.x), "r"(b.y));
}

// ---------------- pre-pass: dtype detect ----------------
__global__ void detect_dtype_kernel(const int* __restrict__ w, long long n_words32) {
    __shared__ int ok;
    if (threadIdx.x == 0) ok = 1;
    __syncthreads();
    const long long pos = 2LL * threadIdx.x + 1;
    if (pos < n_words32) {
        const int v = w[pos];
        if (v != 0 && v != -1) ok = 0;
    }
    __syncthreads();
    if (threadIdx.x == 0) g_neigh_is64 = ok;
}

// ---------------- pre-pass: data -> packed hi|lo bf16 rows ----------------
__global__ void convert_data_kernel(const float* __restrict__ data, int nrows) {
    const int i = blockIdx.x * blockDim.x + threadIdx.x;   // chunk id: row*8 + c
    if (i >= nrows * 8) return;
    const int row = i >> 3, c = i & 7;
    const bool lo = (c >= 4);
    const int e0  = (c & 3) * 8;
    const float4* s = (const float4*)(data + (long long)row * C_IN + e0);
    const float4 f0 = s[0], f1 = s[1];
    const float v[8] = { f0.x, f0.y, f0.z, f0.w, f1.x, f1.y, f1.z, f1.w };
    __nv_bfloat16 h[8];
    #pragma unroll
    for (int j = 0; j < 8; j++) {
        const __nv_bfloat16 hh = __float2bfloat16(v[j]);
        h[j] = lo ? __float2bfloat16(v[j] - __bfloat162float(hh)) : hh;
    }
    *(uint4*)(g_pack + (long long)row * 64 + c * 8) = *(const uint4*)h;
}

// ---------------- pre-pass: weights -> B fragments (mma.m16n8k16 layout) ----------------
// frag f = ((v*2 + s)*4 + nt): v in {hi=0, lo=1}, s = kstep (c_in 16-block), nt = n8 tile.
// lane t holds col n = nt*8 + t/4; rows r0=(t%4)*2, r0+1 (reg .x) and r0+8, r0+9 (reg .y).
__global__ void convert_bfrag_kernel(const float* __restrict__ w) {
    const int i = blockIdx.x * blockDim.x + threadIdx.x;   // (k, f, lane)
    if (i >= KD * 16 * 32) return;
    const int lane = i & 31, f = (i >> 5) & 15, k = i >> 9;
    const int nt = f & 3, s = (f >> 2) & 1, v = f >> 3;
    const int n  = nt * 8 + (lane >> 2);
    const int r0 = (lane & 3) * 2;
    const int rows[4] = { r0, r0 + 1, r0 + 8, r0 + 9 };
    uint16_t h[4];
    #pragma unroll
    for (int j = 0; j < 4; j++) {
        const float x = w[k * C_IN * C_OUT + (s * 16 + rows[j]) * C_OUT + n];
        const __nv_bfloat16 hi = __float2bfloat16(x);
        const __nv_bfloat16 val = (v == 0) ? hi : __float2bfloat16(x - __bfloat162float(hi));
        h[j] = *(const uint16_t*)&val;
    }
    uint2 r;
    r.x = (uint32_t)h[0] | ((uint32_t)h[1] << 16);
    r.y = (uint32_t)h[2] | ((uint32_t)h[3] << 16);
    g_bfrag[(k * 16 + f) * 32 + lane] = r;
}

// ---------------- main: gather + HMMA 3xBF16 ----------------
__global__ __launch_bounds__(TPB) void octconv_hmma_kernel(
    const void* __restrict__ neigh_raw, float* __restrict__ out, int N)
{
    __shared__ __align__(1024) uint8_t sA[2][TM * 128];     // 32KB A tiles (SW128)
    __shared__ __align__(256)  uint8_t sB[2][4096];         // 8KB  B fragment blobs

    const int tid  = threadIdx.x;
    const int warp = tid >> 5;
    const int lane = tid & 31;
    const int base = blockIdx.x * TM;
    const bool is64 = (g_neigh_is64 != 0);
    const int*       n32 = (const int*)neigh_raw;
    const long long* n64 = (const long long*)neigh_raw;

    const uint32_t aAddr[2] = { s2u(&sA[0][0]), s2u(&sA[1][0]) };
    const uint32_t bAddr[2] = { s2u(&sB[0][0]), s2u(&sB[1][0]) };

    // all 27 neighbor indices for this thread's row (local mem; LDL per k)
    int idx[KD];
    {
        const int node = base + tid;
        if (node < N) {
            const long long e0 = (long long)node * KD;
            #pragma unroll
            for (int j = 0; j < KD; j++)
                idx[j] = is64 ? (int)n64[e0 + j] : n32[e0 + j];
        } else {
            #pragma unroll
            for (int j = 0; j < KD; j++) idx[j] = -1;
        }
    }

    float acc[2][4][4];
    #pragma unroll
    for (int mt = 0; mt < 2; mt++)
        #pragma unroll
        for (int nt = 0; nt < 4; nt++)
            #pragma unroll
            for (int e = 0; e < 4; e++) acc[mt][nt][e] = 0.0f;

    // ---- stage-k loader ----
    #define LOADK(k) do {                                                        \
        const int b_ = (k) & 1;                                                  \
        const int id_ = idx[(k)];                                                \
        const int ok_ = (id_ >= 0 && id_ < N);                                   \
        const __nv_bfloat16* src_ = g_pack + (long long)(ok_ ? id_ : 0) * 64;    \
        const uint32_t rb_ = tid * 128;                                          \
        _Pragma("unroll")                                                        \
        for (int c_ = 0; c_ < 8; c_++)                                           \
            cpasync16(aAddr[b_] + SW128(rb_ + c_ * 16), src_ + c_ * 8, ok_ ? 16 : 0); \
        const uint8_t* bs_ = (const uint8_t*)g_bfrag + (k) * 4096;               \
        cpasync16(bAddr[b_] + tid * 16,         bs_ + tid * 16,         16);     \
        cpasync16(bAddr[b_] + (tid + 128) * 16, bs_ + (tid + 128) * 16, 16);     \
        asm volatile("cp.async.commit_group;");                                  \
    } while (0)

    LOADK(0);

    for (int k = 0; k < KD; k++) {
        const int b = k & 1;
        if (k + 1 < KD) {
            LOADK(k + 1);
            asm volatile("cp.async.wait_group 1;" ::: "memory");
        } else {
            asm volatile("cp.async.wait_group 0;" ::: "memory");
        }
        __syncthreads();

        const uint2* bf = (const uint2*)(&sB[b][0]);
        #pragma unroll
        for (int mt = 0; mt < 2; mt++) {
            // ldmatrix.x4 lane address: rows (warp*32 + mt*16 + lane&15), col halves by lane>>4
            const uint32_t rowoff = (uint32_t)((warp * 32 + mt * 16 + (lane & 15)) * 128
                                               + ((lane >> 4) << 4));
            uint32_t ah0[4], ah1[4], al0[4], al1[4];
            ldsm4(ah0, aAddr[b] + SW128(rowoff + 0));    // hi, kstep0
            ldsm4(ah1, aAddr[b] + SW128(rowoff + 32));   // hi, kstep1
            ldsm4(al0, aAddr[b] + SW128(rowoff + 64));   // lo, kstep0
            ldsm4(al1, aAddr[b] + SW128(rowoff + 96));   // lo, kstep1
            #pragma unroll
            for (int nt = 0; nt < 4; nt++) {
                const uint2 bh0 = bf[(0 + nt)  * 32 + lane];   // whi, s0
                const uint2 bh1 = bf[(4 + nt)  * 32 + lane];   // whi, s1
                const uint2 bl0 = bf[(8 + nt)  * 32 + lane];   // wlo, s0
                const uint2 bl1 = bf[(12 + nt) * 32 + lane];   // wlo, s1
                mma16816(acc[mt][nt], ah0, bh0);   // hi*whi
                mma16816(acc[mt][nt], ah1, bh1);
                mma16816(acc[mt][nt], ah0, bl0);   // hi*wlo
                mma16816(acc[mt][nt], ah1, bl1);
                mma16816(acc[mt][nt], al0, bh0);   // lo*whi
                mma16816(acc[mt][nt], al1, bh1);
            }
        }
        __syncthreads();   // buffer b free for load k+2
    }

    // ---- epilogue: C frags -> smem [128][34] -> coalesced store ----
    float* sg = (float*)&sA[0][0];          // 128*34*4 = 17408B (< 32KB of sA)
    #pragma unroll
    for (int mt = 0; mt < 2; mt++) {
        const int r = warp * 32 + mt * 16 + (lane >> 2);
        #pragma unroll
        for (int nt = 0; nt < 4; nt++) {
            const int c = nt * 8 + (lane & 3) * 2;
            *(float2*)(sg + r * 34 + c)       = make_float2(acc[mt][nt][0], acc[mt][nt][1]);
            *(float2*)(sg + (r + 8) * 34 + c) = make_float2(acc[mt][nt][2], acc[mt][nt][3]);
        }
    }
    __syncthreads();
    #pragma unroll 4
    for (int i = 0; i < 32; i++) {
        const int r = warp * 32 + i;
        const int node = base + r;
        if (node < N) out[(long long)node * C_OUT + lane] = sg[r * 34 + lane];
    }
}

extern "C" void kernel_launch(void* const* d_in, const int* in_sizes, int n_in,
                              void* d_out, int out_size)
{
    // Identify inputs by element count: weights=27648 (smallest); data=N*32 (largest); neigh=N*27
    long long s[3] = { (long long)in_sizes[0], (long long)in_sizes[1], (long long)in_sizes[2] };
    int iw  = (s[0] <= s[1] && s[0] <= s[2]) ? 0 : (s[1] <= s[2] ? 1 : 2);
    int idt = (s[0] >= s[1] && s[0] >= s[2]) ? 0 : (s[1] >= s[2] ? 1 : 2);
    if (iw == idt) { iw = 1; idt = 0; }
    int ing = 3 - iw - idt;

    const float* data    = (const float*)d_in[idt];
    const float* weights = (const float*)d_in[iw];
    const void*  neigh   = d_in[ing];
    float*       out     = (float*)d_out;

    const int N = (int)(s[idt] / C_IN);

    detect_dtype_kernel<<<1, 1024>>>((const int*)neigh, s[ing]);
    convert_data_kernel<<<(N * 8 + 255) / 256, 256>>>(data, N);
    convert_bfrag_kernel<<<(KD * 16 * 32 + 255) / 256, 256>>>(weights);
    octconv_hmma_kernel<<<(N + TM - 1) / TM, TPB>>>(neigh, out, N);
}

// round 8
// speedup vs baseline: 3.9068x; 1.1729x over previous
#include <cuda_runtime.h>
#include <cuda_bf16.h>
#include <stdint.h>

#define C_IN   32
#define C_OUT  32
#define KD     27
#define TPB    128
#define TM     128
#define MAXN   262144
#define ARS    144                 // A row stride in smem (bytes): conflict-free ldmatrix
#define STAGE_TX (TM * 128 + 4096) // bulk bytes per stage: A 16KB + B 4KB

// ---------------- device scratch ----------------
__device__ __align__(256) __nv_bfloat16 g_pack[(MAXN + 1) * 64]; // [N+1][128B]: hi|lo; row N = zeros
__device__ __align__(256) uint2 g_bfrag[KD * 16 * 32];           // [k][frag][lane], 4KB per k
__device__ int g_neigh_is64;

// ---------------- helpers ----------------
__device__ __forceinline__ uint32_t s2u(const void* p) {
    uint32_t a;
    asm("{ .reg .u64 t; cvta.to.shared.u64 t, %1; cvt.u32.u64 %0, t; }" : "=r"(a) : "l"(p));
    return a;
}
__device__ __forceinline__ void bulkcp(uint32_t dst, const void* src, uint32_t bytes, uint32_t mbar) {
    asm volatile("cp.async.bulk.shared::cluster.global.mbarrier::complete_tx::bytes "
                 "[%0], [%1], %2, [%3];"
                 :: "r"(dst), "l"(src), "r"(bytes), "r"(mbar) : "memory");
}
__device__ __forceinline__ void ldsm4(uint32_t* r, uint32_t addr) {
    asm volatile("ldmatrix.sync.aligned.m8n8.x4.shared.b16 {%0,%1,%2,%3}, [%4];"
                 : "=r"(r[0]), "=r"(r[1]), "=r"(r[2]), "=r"(r[3]) : "r"(addr));
}
__device__ __forceinline__ void mma16816(float* c, const uint32_t* a, uint2 b) {
    asm volatile("mma.sync.aligned.m16n8k16.row.col.f32.bf16.bf16.f32 "
                 "{%0,%1,%2,%3}, {%4,%5,%6,%7}, {%8,%9}, {%0,%1,%2,%3};"
                 : "+f"(c[0]), "+f"(c[1]), "+f"(c[2]), "+f"(c[3])
                 : "r"(a[0]), "r"(a[1]), "r"(a[2]), "r"(a[3]), "r"(b.x), "r"(b.y));
}
#define MBAR_WAIT(addr, ph) do {                                                      \
    asm volatile("{\n\t.reg .pred P1;\n\t"                                            \
        "WAIT_%=:\n\t"                                                                \
        "mbarrier.try_wait.parity.acquire.cta.shared::cta.b64 P1, [%0], %1, 0x989680;\n\t" \
        "@P1 bra.uni DONE_%=;\n\t"                                                    \
        "bra.uni WAIT_%=;\n\t"                                                        \
        "DONE_%=:\n\t}"                                                               \
        :: "r"(addr), "r"((uint32_t)(ph)) : "memory"); } while (0)

// ---------------- pre-pass: dtype detect ----------------
__global__ void detect_dtype_kernel(const int* __restrict__ w, long long n_words32) {
    __shared__ int ok;
    if (threadIdx.x == 0) ok = 1;
    __syncthreads();
    const long long pos = 2LL * threadIdx.x + 1;
    if (pos < n_words32) {
        const int v = w[pos];
        if (v != 0 && v != -1) ok = 0;
    }
    __syncthreads();
    if (threadIdx.x == 0) g_neigh_is64 = ok;
}

// ---------------- pre-pass: data -> packed hi|lo bf16 rows (+ zero pad row) ----------------
__global__ void convert_data_kernel(const float* __restrict__ data, int nrows) {
    const int i = blockIdx.x * blockDim.x + threadIdx.x;   // chunk id: row*8 + c
    if (i >= (nrows + 1) * 8) return;
    const int row = i >> 3, c = i & 7;
    if (row == nrows) {                                     // zero pad row for invalid neighbors
        *(uint4*)(g_pack + (long long)row * 64 + c * 8) = make_uint4(0, 0, 0, 0);
        return;
    }
    const bool lo = (c >= 4);
    const int e0  = (c & 3) * 8;
    const float4* s = (const float4*)(data + (long long)row * C_IN + e0);
    const float4 f0 = s[0], f1 = s[1];
    const float v[8] = { f0.x, f0.y, f0.z, f0.w, f1.x, f1.y, f1.z, f1.w };
    __nv_bfloat16 h[8];
    #pragma unroll
    for (int j = 0; j < 8; j++) {
        const __nv_bfloat16 hh = __float2bfloat16(v[j]);
        h[j] = lo ? __float2bfloat16(v[j] - __bfloat162float(hh)) : hh;
    }
    *(uint4*)(g_pack + (long long)row * 64 + c * 8) = *(const uint4*)h;
}

// ---------------- pre-pass: weights -> B fragments (mma.m16n8k16 layout) ----------------
__global__ void convert_bfrag_kernel(const float* __restrict__ w) {
    const int i = blockIdx.x * blockDim.x + threadIdx.x;   // (k, f, lane)
    if (i >= KD * 16 * 32) return;
    const int lane = i & 31, f = (i >> 5) & 15, k = i >> 9;
    const int nt = f & 3, s = (f >> 2) & 1, v = f >> 3;
    const int n  = nt * 8 + (lane >> 2);
    const int r0 = (lane & 3) * 2;
    const int rows[4] = { r0, r0 + 1, r0 + 8, r0 + 9 };
    uint16_t h[4];
    #pragma unroll
    for (int j = 0; j < 4; j++) {
        const float x = w[k * C_IN * C_OUT + (s * 16 + rows[j]) * C_OUT + n];
        const __nv_bfloat16 hi = __float2bfloat16(x);
        const __nv_bfloat16 val = (v == 0) ? hi : __float2bfloat16(x - __bfloat162float(hi));
        h[j] = *(const uint16_t*)&val;
    }
    uint2 r;
    r.x = (uint32_t)h[0] | ((uint32_t)h[1] << 16);
    r.y = (uint32_t)h[2] | ((uint32_t)h[3] << 16);
    g_bfrag[(k * 16 + f) * 32 + lane] = r;
}

// ---------------- main: bulk-gather + HMMA 3xBF16 ----------------
__global__ __launch_bounds__(TPB) void octconv_hmma_kernel(
    const void* __restrict__ neigh_raw, float* __restrict__ out, int N)
{
    __shared__ __align__(256) uint8_t sA[2][TM * ARS];      // 36KB A tiles (144B rows)
    __shared__ __align__(256) uint8_t sB[2][4096];          // 8KB  B fragment blobs
    __shared__ __align__(8)  uint64_t smbar[2];

    const int tid  = threadIdx.x;
    const int warp = tid >> 5;
    const int lane = tid & 31;
    const int base = blockIdx.x * TM;
    const bool is64 = (g_neigh_is64 != 0);
    const int*       n32 = (const int*)neigh_raw;
    const long long* n64 = (const long long*)neigh_raw;

    const uint32_t aAddr[2] = { s2u(&sA[0][0]), s2u(&sA[1][0]) };
    const uint32_t bAddr[2] = { s2u(&sB[0][0]), s2u(&sB[1][0]) };
    const uint32_t mAddr[2] = { s2u(&smbar[0]), s2u(&smbar[1]) };

    if (tid == 0) {
        asm volatile("mbarrier.init.shared.b64 [%0], %1;" :: "r"(mAddr[0]), "r"(1u) : "memory");
        asm volatile("mbarrier.init.shared.b64 [%0], %1;" :: "r"(mAddr[1]), "r"(1u) : "memory");
    }
    __syncthreads();

    // all 27 neighbor indices for this thread's row; invalid -> pad row N
    int idx[KD];
    {
        const int node = base + tid;
        if (node < N) {
            const long long e0 = (long long)node * KD;
            #pragma unroll
            for (int j = 0; j < KD; j++) {
                const int v = is64 ? (int)n64[e0 + j] : n32[e0 + j];
                idx[j] = (v >= 0 && v < N) ? v : N;
            }
        } else {
            #pragma unroll
            for (int j = 0; j < KD; j++) idx[j] = N;
        }
    }

    float acc[2][4][4];
    #pragma unroll
    for (int mt = 0; mt < 2; mt++)
        #pragma unroll
        for (int nt = 0; nt < 4; nt++)
            #pragma unroll
            for (int e = 0; e < 4; e++) acc[mt][nt][e] = 0.0f;

    #define ISSUE(k) do {                                                            \
        const int b_ = (k) & 1;                                                      \
        if (tid == 0) {                                                              \
            asm volatile("mbarrier.arrive.expect_tx.shared.b64 _, [%0], %1;"         \
                         :: "r"(mAddr[b_]), "r"((uint32_t)STAGE_TX) : "memory");     \
            bulkcp(bAddr[b_], (const uint8_t*)g_bfrag + (k) * 4096, 4096, mAddr[b_]);\
        }                                                                            \
        bulkcp(aAddr[b_] + tid * ARS,                                                \
               g_pack + (long long)idx[(k)] * 64, 128, mAddr[b_]);                   \
    } while (0)

    ISSUE(0);
    int ph[2] = { 0, 0 };

    for (int k = 0; k < KD; k++) {
        const int b = k & 1;
        if (k + 1 < KD) ISSUE(k + 1);          // buffer b^1 free (syncthreads at k-1 end)
        MBAR_WAIT(mAddr[b], ph[b]);
        ph[b] ^= 1;

        const uint2* bf = (const uint2*)(&sB[b][0]);
        #pragma unroll
        for (int mt = 0; mt < 2; mt++) {
            const uint32_t rowoff = (uint32_t)((warp * 32 + mt * 16 + (lane & 15)) * ARS
                                               + ((lane >> 4) << 4));
            uint32_t ah0[4], ah1[4], al0[4], al1[4];
            ldsm4(ah0, aAddr[b] + rowoff + 0);    // hi, kstep0
            ldsm4(ah1, aAddr[b] + rowoff + 32);   // hi, kstep1
            ldsm4(al0, aAddr[b] + rowoff + 64);   // lo, kstep0
            ldsm4(al1, aAddr[b] + rowoff + 96);   // lo, kstep1
            #pragma unroll
            for (int nt = 0; nt < 4; nt++) {
                const uint2 bh0 = bf[(0 + nt)  * 32 + lane];
                const uint2 bh1 = bf[(4 + nt)  * 32 + lane];
                const uint2 bl0 = bf[(8 + nt)  * 32 + lane];
                const uint2 bl1 = bf[(12 + nt) * 32 + lane];
                mma16816(acc[mt][nt], ah0, bh0);   // hi*whi
                mma16816(acc[mt][nt], ah1, bh1);
                mma16816(acc[mt][nt], ah0, bl0);   // hi*wlo
                mma16816(acc[mt][nt], ah1, bl1);
                mma16816(acc[mt][nt], al0, bh0);   // lo*whi
                mma16816(acc[mt][nt], al1, bh1);
            }
        }
        __syncthreads();   // buffer b consumed by all warps -> free for k+2
    }

    // ---- epilogue: C frags -> smem [128][34] -> coalesced store ----
    float* sg = (float*)&sA[0][0];          // 17408B scratch inside sA
    #pragma unroll
    for (int mt = 0; mt < 2; mt++) {
        const int r = warp * 32 + mt * 16 + (lane >> 2);
        #pragma unroll
        for (int nt = 0; nt < 4; nt++) {
            const int c = nt * 8 + (lane & 3) * 2;
            *(float2*)(sg + r * 34 + c)       = make_float2(acc[mt][nt][0], acc[mt][nt][1]);
            *(float2*)(sg + (r + 8) * 34 + c) = make_float2(acc[mt][nt][2], acc[mt][nt][3]);
        }
    }
    __syncthreads();
    #pragma unroll 4
    for (int i = 0; i < 32; i++) {
        const int r = warp * 32 + i;
        const int node = base + r;
        if (node < N) out[(long long)node * C_OUT + lane] = sg[r * 34 + lane];
    }
}

extern "C" void kernel_launch(void* const* d_in, const int* in_sizes, int n_in,
                              void* d_out, int out_size)
{
    // Identify inputs by element count: weights=27648 (smallest); data=N*32 (largest); neigh=N*27
    long long s[3] = { (long long)in_sizes[0], (long long)in_sizes[1], (long long)in_sizes[2] };
    int iw  = (s[0] <= s[1] && s[0] <= s[2]) ? 0 : (s[1] <= s[2] ? 1 : 2);
    int idt = (s[0] >= s[1] && s[0] >= s[2]) ? 0 : (s[1] >= s[2] ? 1 : 2);
    if (iw == idt) { iw = 1; idt = 0; }
    int ing = 3 - iw - idt;

    const float* data    = (const float*)d_in[idt];
    const float* weights = (const float*)d_in[iw];
    const void*  neigh   = d_in[ing];
    float*       out     = (float*)d_out;

    const int N = (int)(s[idt] / C_IN);

    detect_dtype_kernel<<<1, 1024>>>((const int*)neigh, s[ing]);
    convert_data_kernel<<<((N + 1) * 8 + 255) / 256, 256>>>(data, N);
    convert_bfrag_kernel<<<(KD * 16 * 32 + 255) / 256, 256>>>(weights);
    octconv_hmma_kernel<<<(N + TM - 1) / TM, TPB>>>(neigh, out, N);
}